// round 9
// baseline (speedup 1.0000x reference)
#include <cuda_runtime.h>

#define VDIM 5000
#define MDIM 256
#define NCH 63        // split-K chunks: 63*80 = 5040 >= 5000
#define CHUNK 80
#define LMB 0.001f
#define NITER 2

// ---------------------------------------------------------------------------
// Device scratch (allocation-free rule), 16B-aligned
// ---------------------------------------------------------------------------
__device__ __align__(16) float g_part[2 * NCH * 4 * 64 * 64];
__device__ __align__(16) float g_A[64 * 256], g_T[64 * 256];
__device__ __align__(16) float g_S[4096];
__device__ __align__(16) float g_AAt[4096], g_TA[4096];
__device__ __align__(16) float g_Qm[4096], g_Sinv[4096], g_AAti[4096];
__device__ __align__(16) float g_QtP[4096], g_QtQ[4096], g_U1[4096];
__device__ __align__(16) float g_L3[4096], g_L4[4096];
__device__ __align__(16) float g_R1[4096], g_R2[4096], g_R4[4096];
__device__ __align__(16) float g_X0[4096], g_X[4096];
__device__ __align__(16) float g_M1[4096], g_M2[4096], g_M4[4096];

// ---------------------------------------------------------------------------
// Big GEMMs: A = tx[64,V] @ fx[V,256], T = ty @ fy.  4x4 microtile, split-K.
// ---------------------------------------------------------------------------
__global__ void __launch_bounds__(256) big_gemm(
        const float* __restrict__ fx, const float* __restrict__ fy,
        const float* __restrict__ tx, const float* __restrict__ ty) {
    int ch = blockIdx.x, ct = blockIdx.y, mz = blockIdx.z;
    const float* f = mz ? fy : fx;
    const float* t = mz ? ty : tx;

    __shared__ __align__(16) float tsT[16][68];
    __shared__ __align__(16) float fs[16][64];

    int tid = threadIdx.x;
    int r0 = (tid >> 4) * 4;
    int c0 = (tid & 15) * 4;

    float acc[4][4];
#pragma unroll
    for (int i = 0; i < 4; i++)
#pragma unroll
        for (int j = 0; j < 4; j++) acc[i][j] = 0.f;

    int lr = tid >> 2, lkq = (tid & 3) * 4;
    int fkk = tid >> 4, fcb = (tid & 15) * 4;

    int k0 = ch * CHUNK;
    for (int sub = 0; sub < CHUNK / 16; ++sub) {
        int kb = k0 + sub * 16;
#pragma unroll
        for (int q = 0; q < 4; q++) {
            int k = kb + lkq + q;
            tsT[lkq + q][lr] = (k < VDIM) ? t[lr * VDIM + k] : 0.f;
        }
        {
            int k = kb + fkk;
            float4 fv = make_float4(0.f, 0.f, 0.f, 0.f);
            if (k < VDIM) fv = *(const float4*)&f[k * MDIM + ct * 64 + fcb];
            *(float4*)&fs[fkk][fcb] = fv;
        }
        __syncthreads();
#pragma unroll
        for (int kk = 0; kk < 16; kk++) {
            float4 av = *(const float4*)&tsT[kk][r0];
            float4 bv = *(const float4*)&fs[kk][c0];
            float a[4] = {av.x, av.y, av.z, av.w};
            float b[4] = {bv.x, bv.y, bv.z, bv.w};
#pragma unroll
            for (int i = 0; i < 4; i++)
#pragma unroll
                for (int j = 0; j < 4; j++) acc[i][j] += a[i] * b[j];
        }
        __syncthreads();
    }
    size_t base = (((size_t)mz * NCH + ch) * 4 + ct) * 4096;
#pragma unroll
    for (int i = 0; i < 4; i++)
        *(float4*)&g_part[base + (size_t)(r0 + i) * 64 + c0] =
            make_float4(acc[i][0], acc[i][1], acc[i][2], acc[i][3]);
}

// ---------------------------------------------------------------------------
// Cluster phase barrier
// ---------------------------------------------------------------------------
__device__ __forceinline__ void csync() {
    asm volatile("fence.acq_rel.cluster;" ::: "memory");
    asm volatile("barrier.cluster.arrive.aligned;" ::: "memory");
    asm volatile("barrier.cluster.wait.aligned;" ::: "memory");
}

// ---------------------------------------------------------------------------
// Register-resident Gauss-Jordan 64x64 inversion (no pivoting; SPD / ~I).
// Template recursion makes the pivot index a compile-time constant at every
// step, so all register-array indices are PROVABLY static (no local-memory
// demotion regardless of unroll heuristics).
// ---------------------------------------------------------------------------
struct GJState {
    float (*pr)[128];   // [2][128] pivot row double buffer
    float (*fc)[64];    // [2][64]  pivot col double buffer
    int r, cg, j0;
    float mydiag;
};

template <int P>
__device__ __forceinline__ void gj_step(float (&a)[32], GJState& st) {
    constexpr int cur = P & 1, nxt = cur ^ 1;
    float apiv = st.fc[cur][P];
    float scale = __fdividef(st.fc[cur][st.r], apiv);
    if (st.r == P) st.mydiag = apiv;
    if (st.r != P) {
#pragma unroll
        for (int jj = 0; jj < 32; jj++) a[jj] -= scale * st.pr[cur][st.j0 + jj];
    }
    if (P < 63) {
        constexpr int q = (P + 1) & 63;
        constexpr int qg = q >> 5, qj = q & 31;
        if (st.cg == qg) st.fc[nxt][st.r] = a[qj];   // static index qj
        if (st.r == q) {
#pragma unroll
            for (int jj = 0; jj < 32; jj++) st.pr[nxt][st.j0 + jj] = a[jj];
        }
    }
    __syncthreads();
}

template <int P>
struct GJLoop {
    static __device__ __forceinline__ void run(float (&a)[32], GJState& st) {
        gj_step<P>(a, st);
        GJLoop<P + 1>::run(a, st);
    }
};
template <>
struct GJLoop<64> {
    static __device__ __forceinline__ void run(float (&)[32], GJState&) {}
};

__device__ __noinline__ void gj_inv(const float* __restrict__ Ain, float* __restrict__ Aout) {
    __shared__ float pr[2][128];
    __shared__ float fc[2][64];
    int tid = threadIdx.x;
    GJState st;
    st.pr = pr; st.fc = fc;
    st.r = tid & 63; st.cg = tid >> 6; st.j0 = st.cg * 32;
    st.mydiag = 1.f;
    float a[32];
#pragma unroll
    for (int jj = 0; jj < 32; jj++) {
        int j = st.j0 + jj;
        a[jj] = (j < 64) ? Ain[st.r * 64 + j] : ((j - 64 == st.r) ? 1.f : 0.f);
    }
    if (st.cg == 0) fc[0][st.r] = a[0];
    if (st.r == 0) {
#pragma unroll
        for (int jj = 0; jj < 32; jj++) pr[0][st.j0 + jj] = a[jj];
    }
    __syncthreads();
    GJLoop<0>::run(a, st);
    if (st.cg >= 2) {
        float dinv = 1.f / st.mydiag;
#pragma unroll
        for (int jj = 0; jj < 32; jj++)
            Aout[st.r * 64 + (st.j0 - 64) + jj] = a[jj] * dinv;
    }
}

// ---------------------------------------------------------------------------
// Microtiled helpers: 2x4 register tile, 32-row half-matrix per call.
// ---------------------------------------------------------------------------
__device__ void dot64h(const float* __restrict__ A, const float* __restrict__ B,
                       float* __restrict__ C, int rb, float* __restrict__ C2) {
    int tid = threadIdx.x;
    int r = rb + (tid >> 4) * 2, c0 = (tid & 15) * 4;
    float4 a0 = make_float4(0.f, 0.f, 0.f, 0.f), a1 = a0;
#pragma unroll 4
    for (int k4 = 0; k4 < 16; k4++) {
        float4 x0 = *(const float4*)&A[r * 64 + k4 * 4];
        float4 x1 = *(const float4*)&A[(r + 1) * 64 + k4 * 4];
#pragma unroll
        for (int kk = 0; kk < 4; kk++) {
            float u0 = (kk == 0) ? x0.x : (kk == 1) ? x0.y : (kk == 2) ? x0.z : x0.w;
            float u1 = (kk == 0) ? x1.x : (kk == 1) ? x1.y : (kk == 2) ? x1.z : x1.w;
            float4 bv = *(const float4*)&B[(k4 * 4 + kk) * 64 + c0];
            a0.x += u0 * bv.x; a0.y += u0 * bv.y; a0.z += u0 * bv.z; a0.w += u0 * bv.w;
            a1.x += u1 * bv.x; a1.y += u1 * bv.y; a1.z += u1 * bv.z; a1.w += u1 * bv.w;
        }
    }
    *(float4*)&C[r * 64 + c0] = a0;
    *(float4*)&C[(r + 1) * 64 + c0] = a1;
    if (C2) {
        *(float4*)&C2[r * 64 + c0] = a0;
        *(float4*)&C2[(r + 1) * 64 + c0] = a1;
    }
}

__device__ void dot_nt256h(const float* __restrict__ L, const float* __restrict__ R,
                           float* __restrict__ C, int rb) {
    int tid = threadIdx.x;
    int r = rb + (tid >> 4) * 2, c0 = (tid & 15) * 4;
    float s[2][4];
#pragma unroll
    for (int i = 0; i < 2; i++)
#pragma unroll
        for (int j = 0; j < 4; j++) s[i][j] = 0.f;
#pragma unroll 8
    for (int k4 = 0; k4 < 64; k4++) {
        float4 l0 = *(const float4*)&L[r * 256 + k4 * 4];
        float4 l1 = *(const float4*)&L[(r + 1) * 256 + k4 * 4];
#pragma unroll
        for (int j = 0; j < 4; j++) {
            float4 rv = *(const float4*)&R[(c0 + j) * 256 + k4 * 4];
            s[0][j] += l0.x * rv.x + l0.y * rv.y + l0.z * rv.z + l0.w * rv.w;
            s[1][j] += l1.x * rv.x + l1.y * rv.y + l1.z * rv.z + l1.w * rv.w;
        }
    }
    *(float4*)&C[r * 64 + c0] = make_float4(s[0][0], s[0][1], s[0][2], s[0][3]);
    *(float4*)&C[(r + 1) * 64 + c0] = make_float4(s[1][0], s[1][1], s[1][2], s[1][3]);
}

__device__ void qt_fusedh(const float* __restrict__ ex, int rb) {
    int tid = threadIdx.x;
    int r = rb + (tid >> 4) * 2, c0 = (tid & 15) * 4;
    float4 p0 = make_float4(0.f, 0.f, 0.f, 0.f), p1 = p0;
    float4 q0 = p0, q1 = p0, u0 = p0, u1 = p0;
    for (int k = 0; k < 64; k++) {
        float a0 = g_Qm[k * 64 + r], a1 = g_Qm[k * 64 + r + 1];
        float e = ex[k];
        float4 qc = *(const float4*)&g_Qm[k * 64 + c0];
        float t0 = a0 * e, t1 = a1 * e, w0 = t0 * e, w1 = t1 * e;
        p0.x += t0 * qc.x; p0.y += t0 * qc.y; p0.z += t0 * qc.z; p0.w += t0 * qc.w;
        p1.x += t1 * qc.x; p1.y += t1 * qc.y; p1.z += t1 * qc.z; p1.w += t1 * qc.w;
        q0.x += a0 * qc.x; q0.y += a0 * qc.y; q0.z += a0 * qc.z; q0.w += a0 * qc.w;
        q1.x += a1 * qc.x; q1.y += a1 * qc.y; q1.z += a1 * qc.z; q1.w += a1 * qc.w;
        u0.x += w0 * qc.x; u0.y += w0 * qc.y; u0.z += w0 * qc.z; u0.w += w0 * qc.w;
        u1.x += w1 * qc.x; u1.y += w1 * qc.y; u1.z += w1 * qc.z; u1.w += w1 * qc.w;
    }
    *(float4*)&g_QtP[r * 64 + c0] = p0;
    *(float4*)&g_QtP[(r + 1) * 64 + c0] = p1;
    *(float4*)&g_QtQ[r * 64 + c0] = q0;
    *(float4*)&g_QtQ[(r + 1) * 64 + c0] = q1;
    float4 v0 = *(const float4*)&g_AAt[r * 64 + c0];
    float4 v1 = *(const float4*)&g_AAt[(r + 1) * 64 + c0];
    *(float4*)&g_U1[r * 64 + c0] =
        make_float4(v0.x + LMB * u0.x, v0.y + LMB * u0.y, v0.z + LMB * u0.z, v0.w + LMB * u0.w);
    *(float4*)&g_U1[(r + 1) * 64 + c0] =
        make_float4(v1.x + LMB * u1.x, v1.y + LMB * u1.y, v1.z + LMB * u1.z, v1.w + LMB * u1.w);
}

__device__ void l3l4_unit(const float* __restrict__ ey) {
    int tid = threadIdx.x;
    int c0 = (tid & 15) * 4;
    float4 eyc = *(const float4*)&ey[c0];
    for (int h = 0; h < 2; h++) {
        int r = h * 32 + (tid >> 4) * 2;
        float4 a0 = make_float4(0.f, 0.f, 0.f, 0.f), a1 = a0;
        for (int k = 0; k < 64; k++) {
            float w = ey[k];
            float x0 = g_Sinv[r * 64 + k] * w, x1 = g_Sinv[(r + 1) * 64 + k] * w;
            float4 sv = *(const float4*)&g_S[k * 64 + c0];
            a0.x += x0 * sv.x; a0.y += x0 * sv.y; a0.z += x0 * sv.z; a0.w += x0 * sv.w;
            a1.x += x1 * sv.x; a1.y += x1 * sv.y; a1.z += x1 * sv.z; a1.w += x1 * sv.w;
        }
        float4 l30 = make_float4(LMB * a0.x, LMB * a0.y, LMB * a0.z, LMB * a0.w);
        float4 l31 = make_float4(LMB * a1.x, LMB * a1.y, LMB * a1.z, LMB * a1.w);
        *(float4*)&g_L3[r * 64 + c0] = l30;
        *(float4*)&g_L3[(r + 1) * 64 + c0] = l31;
        *(float4*)&g_L4[r * 64 + c0] =
            make_float4(l30.x * eyc.x, l30.y * eyc.y, l30.z * eyc.z, l30.w * eyc.w);
        *(float4*)&g_L4[(r + 1) * 64 + c0] =
            make_float4(l31.x * eyc.x, l31.y * eyc.y, l31.z * eyc.z, l31.w * eyc.w);
    }
}

__device__ void iterB_slab(int slab, const float* __restrict__ ey, float* __restrict__ out) {
    int tid = threadIdx.x;
    int r = slab * 16 + (tid >> 4), c0 = (tid & 15) * 4;
    float eyr = LMB * ey[r];
    float4 xv = *(const float4*)&g_X[r * 64 + c0];
    float4 x0 = *(const float4*)&g_X0[r * 64 + c0];
    float4 m1 = *(const float4*)&g_M1[r * 64 + c0];
    float4 m2 = *(const float4*)&g_M2[r * 64 + c0];
    float4 s = make_float4(xv.x + x0.x - m1.x + eyr * m2.x,
                           xv.y + x0.y - m1.y + eyr * m2.y,
                           xv.z + x0.z - m1.z + eyr * m2.z,
                           xv.w + x0.w - m1.w + eyr * m2.w);
#pragma unroll 8
    for (int k = 0; k < 64; k++) {
        float l3 = g_L3[r * 64 + k], l4 = g_L4[r * 64 + k];
        float4 a = *(const float4*)&g_M2[k * 64 + c0];
        float4 b = *(const float4*)&g_M4[k * 64 + c0];
        s.x += l3 * a.x - l4 * b.x;  s.y += l3 * a.y - l4 * b.y;
        s.z += l3 * a.z - l4 * b.z;  s.w += l3 * a.w - l4 * b.w;
    }
    *(float4*)&g_X[r * 64 + c0] = s;
    if (out) *(float4*)&out[r * 64 + c0] = s;
}

// ---------------------------------------------------------------------------
// Mega kernel: reduce + all small-matrix work, one 8-CTA cluster.
// ---------------------------------------------------------------------------
__global__ void __cluster_dims__(8, 1, 1) __launch_bounds__(256, 1)
mega(const float* __restrict__ sx, const float* __restrict__ sy,
     const float* __restrict__ ex, const float* __restrict__ ey,
     float* __restrict__ out) {
    int b = blockIdx.x;
    int tid = threadIdx.x;

    // P0: reduce split-K partials (CTA b: mz=b>>2, ct=b&3); CTA0 also S
    {
        int mz = b >> 2, ct = b & 3;
        float* dst = mz ? g_T : g_A;
#pragma unroll
        for (int i = 0; i < 4; i++) {
            int oq = tid + i * 256;
            int r = oq >> 4, c = (oq & 15) * 4;
            float4 s = make_float4(0.f, 0.f, 0.f, 0.f);
#pragma unroll 3
            for (int ch = 0; ch < NCH; ch++) {
                float4 v = *(const float4*)&g_part[(((size_t)mz * NCH + ch) * 4 + ct) * 4096 + r * 64 + c];
                s.x += v.x; s.y += v.y; s.z += v.z; s.w += v.w;
            }
            *(float4*)&dst[r * 256 + ct * 64 + c] = s;
        }
        if (b == 0) {   // S = sy^T sy
            int c0 = (tid & 15) * 4;
            for (int h = 0; h < 2; h++) {
                int r = h * 32 + (tid >> 4) * 2;
                float4 a0 = make_float4(0.f, 0.f, 0.f, 0.f), a1 = a0;
                for (int k = 0; k < 64; k++) {
                    float s0 = sy[k * 64 + r], s1 = sy[k * 64 + r + 1];
                    float4 sc = *(const float4*)&sy[k * 64 + c0];
                    a0.x += s0 * sc.x; a0.y += s0 * sc.y; a0.z += s0 * sc.z; a0.w += s0 * sc.w;
                    a1.x += s1 * sc.x; a1.y += s1 * sc.y; a1.z += s1 * sc.z; a1.w += s1 * sc.w;
                }
                *(float4*)&g_S[r * 64 + c0] = a0;
                *(float4*)&g_S[(r + 1) * 64 + c0] = a1;
            }
        }
    }
    csync();

    // P1: gj(sx), gj(S), AAt (2 halves), TA (2 halves)
    if (b == 0)      gj_inv(sx, g_Qm);
    else if (b == 1) gj_inv(g_S, g_Sinv);
    else if (b < 4)  dot_nt256h(g_A, g_A, g_AAt, (b - 2) * 32);
    else if (b < 6)  dot_nt256h(g_T, g_A, g_TA, (b - 4) * 32);
    csync();

    // P2: gj(AAt) || qt_fused (QtP,QtQ,U1) || L3/L4
    if (b == 0)      gj_inv(g_AAt, g_AAti);
    else if (b < 3)  qt_fusedh(ex, (b - 1) * 32);
    else if (b == 3) l3l4_unit(ey);
    csync();

    // P3: R1, R2, R4, X0 (=TA*AAti, dup to X)
    if (b < 2)      dot64h(g_U1, g_AAti, g_R1, b * 32, 0);
    else if (b < 4) dot64h(g_QtP, g_AAti, g_R2, (b - 2) * 32, 0);
    else if (b < 6) dot64h(g_QtQ, g_AAti, g_R4, (b - 4) * 32, 0);
    else            dot64h(g_TA, g_AAti, g_X0, (b - 6) * 32, g_X);
    csync();

    // Richardson iterations
    for (int it = 0; it < NITER; it++) {
        if (b < 2)      dot64h(g_X, g_R1, g_M1, b * 32, 0);
        else if (b < 4) dot64h(g_X, g_R2, g_M2, (b - 2) * 32, 0);
        else if (b < 6) dot64h(g_X, g_R4, g_M4, (b - 4) * 32, 0);
        csync();
        if (b < 4) iterB_slab(b, ey, (it == NITER - 1) ? out : 0);
        csync();
    }
}

// ---------------------------------------------------------------------------
// Launch: graph-capturable, allocation-free, deterministic.  2 nodes.
// ---------------------------------------------------------------------------
extern "C" void kernel_launch(void* const* d_in, const int* in_sizes, int n_in,
                              void* d_out, int out_size) {
    const float *fx = 0, *fy = 0, *ex = 0, *ey = 0, *tx = 0, *ty = 0, *sx = 0, *sy = 0;
    int nFeat = 0, nEval = 0, nEvec = 0, nSq = 0;
    for (int i = 0; i < n_in; i++) {
        const float* p = (const float*)d_in[i];
        int n = in_sizes[i];
        if (n == VDIM * MDIM)    { if (nFeat++ == 0) fx = p; else fy = p; }
        else if (n == 64)        { if (nEval++ == 0) ex = p; else ey = p; }
        else if (n == 64 * VDIM) { if (nEvec++ == 0) tx = p; else ty = p; }
        else if (n == 64 * 64)   { if (nSq++   == 0) sx = p; else sy = p; }
    }

    dim3 gB(NCH, 4, 2);
    big_gemm<<<gB, 256>>>(fx, fy, tx, ty);
    mega<<<8, 256>>>(sx, sy, ex, ey, (float*)d_out);
}